// round 15
// baseline (speedup 1.0000x reference)
#include <cuda_runtime.h>
#include <cuda_bf16.h>
#include <math.h>
#include <stdint.h>

// ---------------- problem constants ----------------
#define BB   4
#define TTT  4096
#define CC   1024
#define HH   16
#define KK   64
#define TCH  128      // chunk length
#define NCH  32       // chunks = TTT/TCH
#define MM   16384    // BB*TTT rows

// ---------------- scratch (device globals; no allocation allowed) ----------
__device__ __align__(16) __nv_bfloat16 g_Whi[5u*1024u*1024u];   // bf16 hi of weights [z][n][k]
__device__ __align__(16) __nv_bfloat16 g_Wlo[5u*1024u*1024u];   // bf16 lo residuals
__device__ __align__(16) __nv_bfloat16 g_Ahi[4u*16384u*1024u];  // mixed activations hi [z][m][k]
__device__ __align__(16) __nv_bfloat16 g_Alo[4u*16384u*1024u];  // mixed activations lo
__device__ __align__(16) __nv_bfloat16 g_ghi[16384u*1024u];     // gated activations hi
__device__ __align__(16) __nv_bfloat16 g_glo[16384u*1024u];     // gated activations lo
__device__ uint32_t g_r [16384u*1024u];      // packed bf16 hi|lo per element
__device__ uint32_t g_k [16384u*1024u];      // packed
__device__ uint32_t g_v [16384u*1024u];      // packed
__device__ float g_g [16384u*1024u];         // fp32 (gate pre-activation)
__device__ float g_xo[16384u*1024u];
__device__ float g_A [2048u*4096u];          // per-chunk KV outer products
__device__ float g_S [2048u*4096u];          // pre-chunk states

// ---------------- helpers ---------------------------------------------------
__device__ __forceinline__ uint32_t s2u(const void* p) {
    uint32_t a;
    asm("{ .reg .u64 t; cvta.to.shared.u64 t, %1; cvt.u32.u64 %0, t; }"
        : "=r"(a) : "l"(p));
    return a;
}

#define LDSM4(r0,r1,r2,r3,addr) \
    asm volatile("ldmatrix.sync.aligned.m8n8.x4.shared.b16 {%0,%1,%2,%3}, [%4];" \
        : "=r"(r0), "=r"(r1), "=r"(r2), "=r"(r3) : "r"(addr))

#define LDSM4T(r0,r1,r2,r3,addr) \
    asm volatile("ldmatrix.sync.aligned.m8n8.x4.trans.shared.b16 {%0,%1,%2,%3}, [%4];" \
        : "=r"(r0), "=r"(r1), "=r"(r2), "=r"(r3) : "r"(addr))

#define MMA16816(c, a, b0v, b1v) \
    asm volatile("mma.sync.aligned.m16n8k16.row.col.f32.bf16.bf16.f32 " \
        "{%0,%1,%2,%3},{%4,%5,%6,%7},{%8,%9},{%0,%1,%2,%3};" \
        : "+f"((c)[0]), "+f"((c)[1]), "+f"((c)[2]), "+f"((c)[3]) \
        : "r"((a)[0]), "r"((a)[1]), "r"((a)[2]), "r"((a)[3]), "r"(b0v), "r"(b1v))

__device__ __forceinline__ void split_bf16(float v, ushort& h, ushort& l) {
    __nv_bfloat16 hb = __float2bfloat16_rn(v);
    __nv_bfloat16 lb = __float2bfloat16_rn(v - __bfloat162float(hb));
    h = __bfloat16_as_ushort(hb);
    l = __bfloat16_as_ushort(lb);
}

__device__ __forceinline__ uint32_t pack_hilo(float v) {
    ushort h, l;
    split_bf16(v, h, l);
    return (uint32_t)h | ((uint32_t)l << 16);
}

__device__ __forceinline__ float unpack_hilo(uint32_t w) {
    return __bfloat162float(__ushort_as_bfloat16((ushort)(w & 0xffffu)))
         + __bfloat162float(__ushort_as_bfloat16((ushort)(w >> 16)));
}

// ---------------- weight split: all 5 weights in one launch ------------------
__global__ void wconv5(const float* __restrict__ w0, const float* __restrict__ w1,
                       const float* __restrict__ w2, const float* __restrict__ w3,
                       const float* __restrict__ w4) {
    int z = blockIdx.y;
    const float* w = (z==0)?w0:(z==1)?w1:(z==2)?w2:(z==3)?w3:w4;
    size_t i = ((size_t)blockIdx.x * 256 + threadIdx.x) * 4;
    float4 v = *(const float4*)(w + i);
    size_t o = ((size_t)z << 20) + i;
    float vv[4] = {v.x, v.y, v.z, v.w};
    ushort h[4], l[4];
#pragma unroll
    for (int j = 0; j < 4; j++) split_bf16(vv[j], h[j], l[j]);
    uint2 ph = { (uint32_t)h[0] | ((uint32_t)h[1] << 16),
                 (uint32_t)h[2] | ((uint32_t)h[3] << 16) };
    uint2 pl = { (uint32_t)l[0] | ((uint32_t)l[1] << 16),
                 (uint32_t)l[2] | ((uint32_t)l[3] << 16) };
    *(uint2*)&g_Whi[o] = ph;
    *(uint2*)&g_Wlo[o] = pl;
}

// ---------------- premix: time-shift mix + bf16 hi/lo split, all 4 z --------
__global__ __launch_bounds__(256) void premix(
    const float* __restrict__ x,
    const float* __restrict__ mr, const float* __restrict__ mk,
    const float* __restrict__ mv, const float* __restrict__ mg)
{
    int row = blockIdx.x;
    int k = threadIdx.x * 4;
    size_t off = (size_t)row * CC + k;
    float4 xa = *(const float4*)(x + off);
    bool hasprev = (row & (TTT - 1)) != 0;
    float4 xp = hasprev ? *(const float4*)(x + off - CC)
                        : make_float4(0.f, 0.f, 0.f, 0.f);
    const float* mixes[4] = {mr, mk, mv, mg};
#pragma unroll
    for (int z = 0; z < 4; z++) {
        float4 mm = *(const float4*)(mixes[z] + k);
        float v[4] = { xp.x + (xa.x - xp.x)*mm.x,
                       xp.y + (xa.y - xp.y)*mm.y,
                       xp.z + (xa.z - xp.z)*mm.z,
                       xp.w + (xa.w - xp.w)*mm.w };
        ushort h[4], l[4];
#pragma unroll
        for (int j = 0; j < 4; j++) split_bf16(v[j], h[j], l[j]);
        uint2 ph = { (uint32_t)h[0] | ((uint32_t)h[1] << 16),
                     (uint32_t)h[2] | ((uint32_t)h[3] << 16) };
        uint2 pl = { (uint32_t)l[0] | ((uint32_t)l[1] << 16),
                     (uint32_t)l[2] | ((uint32_t)l[3] << 16) };
        size_t o = ((size_t)z << 24) + off;
        *(uint2*)&g_Ahi[o] = ph;
        *(uint2*)&g_Alo[o] = pl;
    }
}

// ---------------- HMMA GEMM core (proven R10/R11 geometry) -------------------
#define RSTR   80u
#define BUFSZ  10240u          // 128 * 80
#define STAGESZ 40960u         // 4 buffers
#define GEMM_SMEM 81920u       // 2 stages

__device__ __forceinline__ void fill_stage(
    uint32_t st, int tid,
    const __nv_bfloat16* __restrict__ Ahi, const __nv_bfloat16* __restrict__ Alo,
    const __nv_bfloat16* __restrict__ Bhi, const __nv_bfloat16* __restrict__ Blo,
    int m0, int n0, int k0)
{
#pragma unroll
    for (int p = 0; p < 8; p++) {
        int idx  = p * 256 + tid;
        int half = idx >> 10;          // 0 = A, 1 = B
        int hl   = (idx >> 9) & 1;     // 0 = hi, 1 = lo
        int r    = (idx >> 2) & 127;
        int c4   = idx & 3;
        const __nv_bfloat16* bsrc = half ? (hl ? Blo : Bhi) : (hl ? Alo : Ahi);
        const __nv_bfloat16* src = bsrc + (size_t)((half ? n0 : m0) + r) * CC + k0 + c4 * 8;
        uint32_t dst = st + (uint32_t)half * 20480u + (uint32_t)hl * BUFSZ
                          + (uint32_t)r * RSTR + (uint32_t)c4 * 16u;
        asm volatile("cp.async.cg.shared.global [%0], [%1], 16;" :: "r"(dst), "l"(src));
    }
    asm volatile("cp.async.commit_group;");
}

template<bool PACKED>
__device__ __forceinline__ void hgemm_core(
    char* sm,
    const __nv_bfloat16* __restrict__ Ahi, const __nv_bfloat16* __restrict__ Alo,
    const __nv_bfloat16* __restrict__ Bhi, const __nv_bfloat16* __restrict__ Blo,
    void* __restrict__ outv, int m0, int n0)
{
    int tid  = threadIdx.x;
    int lane = tid & 31;
    int wid  = tid >> 5;
    int wm   = wid >> 2;      // 0..1
    int wn   = wid & 3;       // 0..3
    uint32_t sb = s2u(sm);

    float acc[4][4][4] = {};

    fill_stage(sb, tid, Ahi, Alo, Bhi, Blo, m0, n0, 0);

#pragma unroll 1
    for (int c = 0; c < 32; c++) {
        if (c < 31) {
            fill_stage(sb + ((c + 1) & 1) * STAGESZ, tid, Ahi, Alo, Bhi, Blo,
                       m0, n0, (c + 1) * 32);
            asm volatile("cp.async.wait_group 1;");
        } else {
            asm volatile("cp.async.wait_group 0;");
        }
        __syncthreads();

        uint32_t st = sb + (c & 1) * STAGESZ;
#pragma unroll
        for (int ks = 0; ks < 2; ks++) {
            uint32_t ah[4][4], al[4][4], bh[4][2], bl[4][2];
#pragma unroll
            for (int mf = 0; mf < 4; mf++) {
                uint32_t ad = st + (uint32_t)(wm*64 + mf*16 + (lane & 15)) * RSTR
                                 + (uint32_t)ks * 32u + (uint32_t)((lane >> 4) << 4);
                LDSM4(ah[mf][0], ah[mf][1], ah[mf][2], ah[mf][3], ad);
                LDSM4(al[mf][0], al[mf][1], al[mf][2], al[mf][3], ad + BUFSZ);
            }
#pragma unroll
            for (int g2 = 0; g2 < 2; g2++) {
                uint32_t bd = st + 20480u
                    + (uint32_t)(wn*32 + g2*16 + (lane & 7) + ((lane >> 4) << 3)) * RSTR
                    + (uint32_t)ks * 32u + (uint32_t)(((lane >> 3) & 1) << 4);
                uint32_t t0, t1, t2, t3;
                LDSM4(t0, t1, t2, t3, bd);
                bh[g2*2][0] = t0; bh[g2*2][1] = t1;
                bh[g2*2+1][0] = t2; bh[g2*2+1][1] = t3;
                LDSM4(t0, t1, t2, t3, bd + BUFSZ);
                bl[g2*2][0] = t0; bl[g2*2][1] = t1;
                bl[g2*2+1][0] = t2; bl[g2*2+1][1] = t3;
            }
#pragma unroll
            for (int mf = 0; mf < 4; mf++)
#pragma unroll
                for (int nf = 0; nf < 4; nf++) {
                    MMA16816(acc[mf][nf], ah[mf], bh[nf][0], bh[nf][1]);
                    MMA16816(acc[mf][nf], ah[mf], bl[nf][0], bl[nf][1]);
                    MMA16816(acc[mf][nf], al[mf], bh[nf][0], bh[nf][1]);
                }
        }
        __syncthreads();
    }

#pragma unroll
    for (int mf = 0; mf < 4; mf++) {
        int row = m0 + wm*64 + mf*16 + (lane >> 2);
#pragma unroll
        for (int nf = 0; nf < 4; nf++) {
            int col = n0 + wn*32 + nf*8 + ((lane & 3) << 1);
            if (PACKED) {
                uint32_t* out = (uint32_t*)outv;
                *(uint2*)&out[(size_t)row * CC + col] =
                    make_uint2(pack_hilo(acc[mf][nf][0]), pack_hilo(acc[mf][nf][1]));
                *(uint2*)&out[(size_t)(row + 8) * CC + col] =
                    make_uint2(pack_hilo(acc[mf][nf][2]), pack_hilo(acc[mf][nf][3]));
            } else {
                float* out = (float*)outv;
                *(float2*)&out[(size_t)row * CC + col] =
                    make_float2(acc[mf][nf][0], acc[mf][nf][1]);
                *(float2*)&out[(size_t)(row + 8) * CC + col] =
                    make_float2(acc[mf][nf][2], acc[mf][nf][3]);
            }
        }
    }
}

// r/k/v projections -> packed hi|lo words
__global__ __launch_bounds__(256, 2) void hgemm_z_pk(int zbase)
{
    extern __shared__ char dyn[];
    int z = zbase + blockIdx.z;
    void* out = (z==0) ? (void*)g_r : (z==1) ? (void*)g_k : (void*)g_v;
    hgemm_core<true>(dyn,
               g_Ahi + ((size_t)z << 24), g_Alo + ((size_t)z << 24),
               g_Whi + ((size_t)z << 20), g_Wlo + ((size_t)z << 20),
               out, blockIdx.y * 128, blockIdx.x * 128);
}

// g projection -> fp32
__global__ __launch_bounds__(256, 2) void hgemm_g()
{
    extern __shared__ char dyn[];
    hgemm_core<false>(dyn,
               g_Ahi + (3ull << 24), g_Alo + (3ull << 24),
               g_Whi + (3ull << 20), g_Wlo + (3ull << 20),
               g_g, blockIdx.y * 128, blockIdx.x * 128);
}

__global__ __launch_bounds__(256, 2) void hgemm_o(float* __restrict__ out)
{
    extern __shared__ char dyn[];
    hgemm_core<false>(dyn, g_ghi, g_glo,
               g_Whi + (4ull << 20), g_Wlo + (4ull << 20),
               out, blockIdx.y * 128, blockIdx.x * 128);
}

// ---------------- pass 1 (HMMA): A_c = (k.wk)^T @ v --------------------------
// smem: KH/KL/VH/VL each 128 rows x 144B
#define P1_RB   144u
#define P1_KH   0u
#define P1_VH   36864u
#define P1_SMEM 73728u

__global__ __launch_bounds__(256) void pass1_mma(const float* __restrict__ td)
{
    extern __shared__ char sm1[];
    __shared__ float dpow[129];
    uint32_t sb = s2u(sm1);
    int tid = threadIdx.x, lane = tid & 31, wid = tid >> 5;
    int wm = wid >> 2, wn = wid & 3;      // warp: 32-kappa half x 16-nu quarter
    int gid = blockIdx.x;
    int c = gid & 31, bh = gid >> 5, b = bh >> 4, h = bh & 15;

    float lam = expf(td[h]);
    if (tid < 129) dpow[tid] = expf(-lam * (float)tid);
    __syncthreads();

    size_t rowbase = ((size_t)b*TTT + (size_t)c*TCH)*CC + (size_t)h*KK;

    // k: unpack hi+lo, scale by wk[j]=dpow[127-j], re-split
#pragma unroll
    for (int p = 0; p < 8; p++) {
        int e = p * 256 + tid;           // uint4 unit (4 elements)
        int row = e >> 4;
        int col4 = (e & 15) * 4;
        uint4 w = *(const uint4*)(g_k + rowbase + (size_t)row * CC + col4);
        float s = dpow[127 - row];
        uint32_t ws[4] = {w.x, w.y, w.z, w.w};
        ushort hh[4], ll[4];
#pragma unroll
        for (int j = 0; j < 4; j++)
            split_bf16(unpack_hilo(ws[j]) * s, hh[j], ll[j]);
        uint2 ph = { (uint32_t)hh[0] | ((uint32_t)hh[1] << 16),
                     (uint32_t)hh[2] | ((uint32_t)hh[3] << 16) };
        uint2 pl = { (uint32_t)ll[0] | ((uint32_t)ll[1] << 16),
                     (uint32_t)ll[2] | ((uint32_t)ll[3] << 16) };
        uint32_t off = P1_KH + (uint32_t)row * P1_RB + (uint32_t)col4 * 2u;
        *(uint2*)(sm1 + off)          = ph;
        *(uint2*)(sm1 + off + 18432u) = pl;
    }
    // v: unpack-copy (planes separate)
#pragma unroll
    for (int p = 0; p < 8; p++) {
        int e = p * 256 + tid;
        int row = e >> 4;
        int col4 = (e & 15) * 4;
        uint4 w = *(const uint4*)(g_v + rowbase + (size_t)row * CC + col4);
        uint32_t h01 = __byte_perm(w.x, w.y, 0x5410);
        uint32_t h23 = __byte_perm(w.z, w.w, 0x5410);
        uint32_t l01 = __byte_perm(w.x, w.y, 0x7632);
        uint32_t l23 = __byte_perm(w.z, w.w, 0x7632);
        uint32_t off = P1_VH + (uint32_t)row * P1_RB + (uint32_t)col4 * 2u;
        *(uint2*)(sm1 + off)          = make_uint2(h01, h23);
        *(uint2*)(sm1 + off + 18432u) = make_uint2(l01, l23);
    }
    __syncthreads();

    float acc[2][2][4] = {};
#pragma unroll
    for (int ks = 0; ks < 8; ks++) {
        uint32_t ah[2][4], al[2][4];
#pragma unroll
        for (int mf = 0; mf < 2; mf++) {
            int jrow = ks*16 + (lane & 7) + ((lane >> 4) << 3);
            int kcol = wm*32 + mf*16 + (((lane >> 3) & 1) << 3);
            uint32_t ad = sb + P1_KH + (uint32_t)jrow * P1_RB + (uint32_t)kcol * 2u;
            LDSM4T(ah[mf][0], ah[mf][1], ah[mf][2], ah[mf][3], ad);
            LDSM4T(al[mf][0], al[mf][1], al[mf][2], al[mf][3], ad + 18432u);
        }
        uint32_t bd = sb + P1_VH + (uint32_t)(ks*16 + (lane & 15)) * P1_RB
                    + (uint32_t)(wn*16 + ((lane >> 4) << 3)) * 2u;
        uint32_t th0, th1, th2, th3, tl0, tl1, tl2, tl3;
        LDSM4T(th0, th1, th2, th3, bd);
        LDSM4T(tl0, tl1, tl2, tl3, bd + 18432u);
#pragma unroll
        for (int mf = 0; mf < 2; mf++) {
            MMA16816(acc[mf][0], ah[mf], th0, th1);
            MMA16816(acc[mf][0], ah[mf], tl0, tl1);
            MMA16816(acc[mf][0], al[mf], th0, th1);
            MMA16816(acc[mf][1], ah[mf], th2, th3);
            MMA16816(acc[mf][1], ah[mf], tl2, tl3);
            MMA16816(acc[mf][1], al[mf], th2, th3);
        }
    }

    size_t ob = (size_t)gid * 4096;
#pragma unroll
    for (int mf = 0; mf < 2; mf++) {
        int kap = wm*32 + mf*16 + (lane >> 2);
#pragma unroll
        for (int n8 = 0; n8 < 2; n8++) {
            int nu = wn*16 + n8*8 + ((lane & 3) << 1);
            *(float2*)&g_A[ob + (size_t)kap*64 + nu] =
                make_float2(acc[mf][n8][0], acc[mf][n8][1]);
            *(float2*)&g_A[ob + (size_t)(kap+8)*64 + nu] =
                make_float2(acc[mf][n8][2], acc[mf][n8][3]);
        }
    }
}

// ---------------- pass 2: sequential state scan per (b,h) -----------------
__global__ __launch_bounds__(256) void scan_state(const float* __restrict__ td)
{
    int bh = blockIdx.x;
    int h = bh & 15;
    float ws = expf(-expf(td[h]) * (float)TCH);   // decay^T
    int tid = threadIdx.x;
    float s[16];
    #pragma unroll
    for (int e = 0; e < 16; e++) s[e] = 0.f;
    for (int c = 0; c < NCH; c++) {
        size_t base = ((size_t)bh*NCH + c) * 4096;
        #pragma unroll
        for (int e = 0; e < 16; e++) {
            int idx = tid + e*256;
            g_S[base + idx] = s[e];                    // pre-chunk state
            s[e] = ws*s[e] + g_A[base + idx];
        }
    }
}

// ---------------- pass 3 (HMMA): out = ((r@k^T).w)@v + diag(dpow)*(r@S) ----
#define P3_RB   144u
#define P3_RH   0u
#define P3_KH   36864u
#define P3_VH   73728u
#define P3_SH   110592u
#define P3_AB   272u
#define P3_AH   129024u
#define P3_SMEM 198656u

__global__ __launch_bounds__(256) void pass3_mma(const float* __restrict__ td,
                                                 const float* __restrict__ tf)
{
    extern __shared__ char sm3[];
    __shared__ float dpow[129];
    uint32_t sb = s2u(sm3);
    int tid = threadIdx.x, lane = tid & 31, wid = tid >> 5;
    int wm = wid >> 2, wn = wid & 3;
    int gid = blockIdx.x;
    int c = gid & 31, bh = gid >> 5, b = bh >> 4, h = bh & 15;

    float lam = expf(td[h]);
    if (tid < 129) dpow[tid] = expf(-lam * (float)tid);
    float u = tf[h];

    size_t rowbase = ((size_t)b*TTT + (size_t)c*TCH)*CC + (size_t)h*KK;

    // r,k,v: unpack-copy packed words into hi/lo planes
#pragma unroll 4
    for (int p = 0; p < 24; p++) {
        int idx = p * 256 + tid;
        int which = idx >> 11;
        int e = idx & 2047;
        int row = e >> 4;
        int col4 = (e & 15) * 4;
        const uint32_t* src = (which==0 ? g_r : which==1 ? g_k : g_v)
                            + rowbase + (size_t)row * CC + col4;
        uint4 w = *(const uint4*)src;
        uint32_t h01 = __byte_perm(w.x, w.y, 0x5410);
        uint32_t h23 = __byte_perm(w.z, w.w, 0x5410);
        uint32_t l01 = __byte_perm(w.x, w.y, 0x7632);
        uint32_t l23 = __byte_perm(w.z, w.w, 0x7632);
        uint32_t off = (which==0 ? P3_RH : which==1 ? P3_KH : P3_VH)
                     + (uint32_t)row * P3_RB + (uint32_t)col4 * 2u;
        *(uint2*)(sm3 + off)          = make_uint2(h01, h23);
        *(uint2*)(sm3 + off + 18432u) = make_uint2(l01, l23);
    }
    size_t sbase = (size_t)gid * 4096;
#pragma unroll
    for (int p = 0; p < 4; p++) {
        int e = p * 256 + tid;
        int row = e >> 4;
        int col4 = (e & 15) * 4;
        float4 v4 = *(const float4*)(g_S + sbase + (size_t)row * 64 + col4);
        float vv[4] = {v4.x, v4.y, v4.z, v4.w};
        ushort hh[4], ll[4];
#pragma unroll
        for (int j = 0; j < 4; j++) split_bf16(vv[j], hh[j], ll[j]);
        uint2 ph = { (uint32_t)hh[0] | ((uint32_t)hh[1] << 16),
                     (uint32_t)hh[2] | ((uint32_t)hh[3] << 16) };
        uint2 pl = { (uint32_t)ll[0] | ((uint32_t)ll[1] << 16),
                     (uint32_t)ll[2] | ((uint32_t)ll[3] << 16) };
        uint32_t off = P3_SH + (uint32_t)row * P3_RB + (uint32_t)col4 * 2u;
        *(uint2*)(sm3 + off)         = ph;
        *(uint2*)(sm3 + off + 9216u) = pl;
    }
    __syncthreads();

    // ---- stage A: att = (r@k^T) * w_mat ----
    {
        float accA[4][4][4] = {};
#pragma unroll
        for (int ks = 0; ks < 4; ks++) {
            uint32_t ahf[4][4], alf[4][4], bhf[4][2], blf[4][2];
#pragma unroll
            for (int mf = 0; mf < 4; mf++) {
                uint32_t ad = sb + P3_RH
                    + (uint32_t)(wm*64 + mf*16 + (lane & 15)) * P3_RB
                    + (uint32_t)ks * 32u + (uint32_t)((lane >> 4) << 4);
                LDSM4(ahf[mf][0], ahf[mf][1], ahf[mf][2], ahf[mf][3], ad);
                LDSM4(alf[mf][0], alf[mf][1], alf[mf][2], alf[mf][3], ad + 18432u);
            }
#pragma unroll
            for (int g2 = 0; g2 < 2; g2++) {
                uint32_t bd = sb + P3_KH
                    + (uint32_t)(wn*32 + g2*16 + (lane & 7) + ((lane >> 4) << 3)) * P3_RB
                    + (uint32_t)ks * 32u + (uint32_t)(((lane >> 3) & 1) << 4);
                uint32_t t0, t1, t2, t3;
                LDSM4(t0, t1, t2, t3, bd);
                bhf[g2*2][0] = t0; bhf[g2*2][1] = t1;
                bhf[g2*2+1][0] = t2; bhf[g2*2+1][1] = t3;
                LDSM4(t0, t1, t2, t3, bd + 18432u);
                blf[g2*2][0] = t0; blf[g2*2][1] = t1;
                blf[g2*2+1][0] = t2; blf[g2*2+1][1] = t3;
            }
#pragma unroll
            for (int mf = 0; mf < 4; mf++)
#pragma unroll
                for (int nf = 0; nf < 4; nf++) {
                    MMA16816(accA[mf][nf], ahf[mf], bhf[nf][0], bhf[nf][1]);
                    MMA16816(accA[mf][nf], ahf[mf], blf[nf][0], blf[nf][1]);
                    MMA16816(accA[mf][nf], alf[mf], bhf[nf][0], bhf[nf][1]);
                }
        }
#pragma unroll
        for (int mf = 0; mf < 4; mf++) {
            int gi = wm*64 + mf*16 + (lane >> 2);
#pragma unroll
            for (int nf = 0; nf < 4; nf++) {
                int gj = wn*32 + nf*8 + ((lane & 3) << 1);
                float av[4];
#pragma unroll
                for (int e = 0; e < 4; e++) {
                    int ri = gi + ((e >> 1) << 3);
                    int cj = gj + (e & 1);
                    int d = ri - cj;
                    float w = (d > 0) ? dpow[d-1] : ((d == 0) ? u : 0.f);
                    av[e] = accA[mf][nf][e] * w;
                }
                ushort hh[4], ll[4];
#pragma unroll
                for (int e = 0; e < 4; e++) split_bf16(av[e], hh[e], ll[e]);
                uint32_t o0 = P3_AH + (uint32_t)gi * P3_AB + (uint32_t)gj * 2u;
                uint32_t o8 = o0 + 8u * P3_AB;
                *(uint32_t*)(sm3 + o0)           = (uint32_t)hh[0] | ((uint32_t)hh[1] << 16);
                *(uint32_t*)(sm3 + o0 + 34816u)  = (uint32_t)ll[0] | ((uint32_t)ll[1] << 16);
                *(uint32_t*)(sm3 + o8)           = (uint32_t)hh[2] | ((uint32_t)hh[3] << 16);
                *(uint32_t*)(sm3 + o8 + 34816u)  = (uint32_t)ll[2] | ((uint32_t)ll[3] << 16);
            }
        }
    }
    __syncthreads();

    // ---- stage B: out = att@v + diag(dpow)*(r@S) ----
    {
        float acc2[4][2][4] = {};
        float acc3[4][2][4] = {};
#pragma unroll
        for (int ks = 0; ks < 8; ks++) {
            uint32_t af[4][4], alf2[4][4];
#pragma unroll
            for (int mf = 0; mf < 4; mf++) {
                uint32_t ad = sb + P3_AH
                    + (uint32_t)(wm*64 + mf*16 + (lane & 15)) * P3_AB
                    + (uint32_t)ks * 32u + (uint32_t)((lane >> 4) << 4);
                LDSM4(af[mf][0], af[mf][1], af[mf][2], af[mf][3], ad);
                LDSM4(alf2[mf][0], alf2[mf][1], alf2[mf][2], alf2[mf][3], ad + 34816u);
            }
            uint32_t bd = sb + P3_VH
                + (uint32_t)(ks*16 + (lane & 15)) * P3_RB
                + (uint32_t)(wn*16 + ((lane >> 4) << 3)) * 2u;
            uint32_t th0, th1, th2, th3, tl0, tl1, tl2, tl3;
            LDSM4T(th0, th1, th2, th3, bd);
            LDSM4T(tl0, tl1, tl2, tl3, bd + 18432u);
#pragma unroll
            for (int mf = 0; mf < 4; mf++) {
                MMA16816(acc2[mf][0], af[mf],   th0, th1);
                MMA16816(acc2[mf][0], af[mf],   tl0, tl1);
                MMA16816(acc2[mf][0], alf2[mf], th0, th1);
                MMA16816(acc2[mf][1], af[mf],   th2, th3);
                MMA16816(acc2[mf][1], af[mf],   tl2, tl3);
                MMA16816(acc2[mf][1], alf2[mf], th2, th3);
            }
        }
#pragma unroll
        for (int ks = 0; ks < 4; ks++) {
            uint32_t af[4][4], alf2[4][4];
#pragma unroll
            for (int mf = 0; mf < 4; mf++) {
                uint32_t ad = sb + P3_RH
                    + (uint32_t)(wm*64 + mf*16 + (lane & 15)) * P3_RB
                    + (uint32_t)ks * 32u + (uint32_t)((lane >> 4) << 4);
                LDSM4(af[mf][0], af[mf][1], af[mf][2], af[mf][3], ad);
                LDSM4(alf2[mf][0], alf2[mf][1], alf2[mf][2], alf2[mf][3], ad + 18432u);
            }
            uint32_t bd = sb + P3_SH
                + (uint32_t)(ks*16 + (lane & 15)) * P3_RB
                + (uint32_t)(wn*16 + ((lane >> 4) << 3)) * 2u;
            uint32_t th0, th1, th2, th3, tl0, tl1, tl2, tl3;
            LDSM4T(th0, th1, th2, th3, bd);
            LDSM4T(tl0, tl1, tl2, tl3, bd + 9216u);
#pragma unroll
            for (int mf = 0; mf < 4; mf++) {
                MMA16816(acc3[mf][0], af[mf],   th0, th1);
                MMA16816(acc3[mf][0], af[mf],   tl0, tl1);
                MMA16816(acc3[mf][0], alf2[mf], th0, th1);
                MMA16816(acc3[mf][1], af[mf],   th2, th3);
                MMA16816(acc3[mf][1], af[mf],   tl2, tl3);
                MMA16816(acc3[mf][1], alf2[mf], th2, th3);
            }
        }
#pragma unroll
        for (int mf = 0; mf < 4; mf++) {
            int gi = wm*64 + mf*16 + (lane >> 2);
            float w0 = dpow[gi], w8 = dpow[gi + 8];
#pragma unroll
            for (int nf = 0; nf < 2; nf++) {
                int nu = wn*16 + nf*8 + ((lane & 3) << 1);
                size_t ro = rowbase + (size_t)gi * CC + nu;
                *(float2*)(g_xo + ro) = make_float2(
                    acc2[mf][nf][0] + w0 * acc3[mf][nf][0],
                    acc2[mf][nf][1] + w0 * acc3[mf][nf][1]);
                *(float2*)(g_xo + ro + 8u * CC) = make_float2(
                    acc2[mf][nf][2] + w8 * acc3[mf][nf][2],
                    acc2[mf][nf][3] + w8 * acc3[mf][nf][3]);
            }
        }
    }
}

// ---------------- GroupNorm + SiLU gate -> bf16 hi/lo ----------------------
__global__ void gn_gate(const float* __restrict__ lw, const float* __restrict__ lb)
{
    int grp = blockIdx.x*8 + threadIdx.y;     // (b*TT+t)*H + h
    int h = grp & 15;
    size_t base = (size_t)(grp >> 4)*CC + (size_t)h*KK;
    int lane = threadIdx.x;

    float v0 = g_xo[base + lane]      * 0.125f;
    float v1 = g_xo[base + lane + 32] * 0.125f;
    float sum = v0 + v1;
    float sq  = v0*v0 + v1*v1;
    #pragma unroll
    for (int off = 16; off > 0; off >>= 1) {
        sum += __shfl_xor_sync(0xffffffffu, sum, off);
        sq  += __shfl_xor_sync(0xffffffffu, sq,  off);
    }
    float mu  = sum * (1.f/64.f);
    float var = sq * (1.f/64.f) - mu*mu;
    float inv = rsqrtf(var + 1e-5f);

    float y0 = (v0 - mu)*inv*lw[h*KK + lane]      + lb[h*KK + lane];
    float y1 = (v1 - mu)*inv*lw[h*KK + lane + 32] + lb[h*KK + lane + 32];

    float gg0 = g_g[base + lane];
    float gg1 = g_g[base + lane + 32];
    y0 *= gg0 / (1.f + expf(-gg0));
    y1 *= gg1 / (1.f + expf(-gg1));

    ushort h0, l0, h1, l1;
    split_bf16(y0, h0, l0);
    split_bf16(y1, h1, l1);
    g_ghi[base + lane]      = __ushort_as_bfloat16(h0);
    g_glo[base + lane]      = __ushort_as_bfloat16(l0);
    g_ghi[base + lane + 32] = __ushort_as_bfloat16(h1);
    g_glo[base + lane + 32] = __ushort_as_bfloat16(l1);
}

// ---------------- launch: fork-join multi-stream graph ----------------------
extern "C" void kernel_launch(void* const* d_in, const int* in_sizes, int n_in,
                              void* d_out, int out_size)
{
    const float* x  = (const float*)d_in[0];
    const float* mk = (const float*)d_in[1];
    const float* mv = (const float*)d_in[2];
    const float* mr = (const float*)d_in[3];
    const float* mg = (const float*)d_in[4];
    const float* td = (const float*)d_in[5];
    const float* tf = (const float*)d_in[6];
    const float* Wr = (const float*)d_in[7];
    const float* Wk = (const float*)d_in[8];
    const float* Wv = (const float*)d_in[9];
    const float* Wg = (const float*)d_in[10];
    const float* Wo = (const float*)d_in[11];
    const float* lw = (const float*)d_in[12];
    const float* lb = (const float*)d_in[13];
    float* out = (float*)d_out;

    static cudaStream_t s1 = nullptr, s2 = nullptr;
    static cudaEvent_t ev0, evW, evP, evR, evG, evS1;
    if (!s1) {
        cudaStreamCreateWithFlags(&s1, cudaStreamNonBlocking);
        cudaStreamCreateWithFlags(&s2, cudaStreamNonBlocking);
        cudaEventCreateWithFlags(&ev0, cudaEventDisableTiming);
        cudaEventCreateWithFlags(&evW, cudaEventDisableTiming);
        cudaEventCreateWithFlags(&evP, cudaEventDisableTiming);
        cudaEventCreateWithFlags(&evR, cudaEventDisableTiming);
        cudaEventCreateWithFlags(&evG, cudaEventDisableTiming);
        cudaEventCreateWithFlags(&evS1, cudaEventDisableTiming);
        cudaFuncSetAttribute(pass3_mma, cudaFuncAttributeMaxDynamicSharedMemorySize, (int)P3_SMEM);
        cudaFuncSetAttribute(pass1_mma, cudaFuncAttributeMaxDynamicSharedMemorySize, (int)P1_SMEM);
        cudaFuncSetAttribute(hgemm_z_pk, cudaFuncAttributeMaxDynamicSharedMemorySize, (int)GEMM_SMEM);
        cudaFuncSetAttribute(hgemm_g,   cudaFuncAttributeMaxDynamicSharedMemorySize, (int)GEMM_SMEM);
        cudaFuncSetAttribute(hgemm_o,   cudaFuncAttributeMaxDynamicSharedMemorySize, (int)GEMM_SMEM);
    }

    // fork from the capture-origin (default) stream
    cudaEventRecord(ev0, 0);
    cudaStreamWaitEvent(s1, ev0, 0);
    cudaStreamWaitEvent(s2, ev0, 0);

    // s2: weight split
    wconv5<<<dim3(1024, 5), 256, 0, s2>>>(Wr, Wk, Wv, Wg, Wo);
    cudaEventRecord(evW, s2);

    // s1: activation premix
    premix<<<MM, 256, 0, s1>>>(x, mr, mk, mv, mg);
    cudaEventRecord(evP, s1);

    // s1: k,v projection GEMMs (need weights)
    cudaStreamWaitEvent(s1, evW, 0);
    hgemm_z_pk<<<dim3(8, 128, 2), 256, GEMM_SMEM, s1>>>(1);   // z = 1,2 (k, v)

    // s2: r then g projection GEMMs (need premix)
    cudaStreamWaitEvent(s2, evP, 0);
    hgemm_z_pk<<<dim3(8, 128, 1), 256, GEMM_SMEM, s2>>>(0);   // z = 0 (r)
    cudaEventRecord(evR, s2);
    hgemm_g<<<dim3(8, 128), 256, GEMM_SMEM, s2>>>();          // z = 3 (g)
    cudaEventRecord(evG, s2);

    // s1: attention pipeline (overlaps r/g GEMMs on s2)
    pass1_mma<<<2048, 256, P1_SMEM, s1>>>(td);
    scan_state<<<64, 256, 0, s1>>>(td);
    cudaStreamWaitEvent(s1, evR, 0);                          // pass3 needs r
    pass3_mma<<<2048, 256, P3_SMEM, s1>>>(td, tf);
    cudaEventRecord(evS1, s1);

    // join back on origin stream
    cudaStreamWaitEvent(0, evS1, 0);
    cudaStreamWaitEvent(0, evG, 0);
    gn_gate<<<BB*TTT*HH/8, dim3(32, 8)>>>(lw, lb);
    hgemm_o<<<dim3(8, 128), 256, GEMM_SMEM>>>(out);
}